// round 6
// baseline (speedup 1.0000x reference)
#include <cuda_runtime.h>

// CRF NLL, B=256, S=256, T=128 (126 tags + START/STOP)
// Scaled-probability forward recursion, E = exp(transitions) in registers.
//   s_j  = sum_i w_i * E[i][j]
//   w'_j = s_j * exp(f_j) / (128 * w0)     (w0 = w[0], broadcast)
//   N   += log(w0) + log(128)              (p_j = N + log w_j at the end)
// Feat load and its exp are in DIFFERENT iterations (no LDG->MUFU stall on
// the step path). 8 packed accumulators. LPT schedule + fused final reduce.

#define B_   256
#define S_   256
#define T_   128
#define LOG128 4.852030263919617f

__device__ float g_partial[B_];
__device__ int   g_sched[B_];    // (len << 16) | batch, descending by len
__device__ unsigned g_ticket;    // zero-initialized; reset by last CTA

#define FMA2(d, a, b, c) \
    asm("fma.rn.f32x2 %0, %1, %2, %3;" : "=l"(d) : "l"(a), "l"(b), "l"(c))
#define ADD2(d, a, b) \
    asm("add.rn.f32x2 %0, %1, %2;" : "=l"(d) : "l"(a), "l"(b))
#define PACK2(d, lo, hi) \
    asm("mov.b64 %0, {%1, %2};" : "=l"(d) : "f"(lo), "f"(hi))
#define UNPACK2(lo, hi, s) \
    asm("mov.b64 {%0, %1}, %2;" : "=f"(lo), "=f"(hi) : "l"(s))

__device__ __forceinline__ float warpMax(float x) {
#pragma unroll
    for (int o = 16; o; o >>= 1) x = fmaxf(x, __shfl_xor_sync(0xffffffffu, x, o));
    return x;
}
__device__ __forceinline__ float warpSum(float x) {
#pragma unroll
    for (int o = 16; o; o >>= 1) x += __shfl_xor_sync(0xffffffffu, x, o);
    return x;
}

// ---- prep: binary-search lengths + bitonic sort (desc) -> g_sched ----
__global__ void prep_kernel(const int* __restrict__ mask) {
    __shared__ unsigned key[B_];
    const int b = threadIdx.x;
    const int* mb = mask + b * S_;
    int lo = S_ / 2, hi = S_;               // len in [S/2, S], prefix mask
    while (lo < hi) {                       // 7 iterations
        int mid = (lo + hi) >> 1;
        if (mb[mid]) lo = mid + 1; else hi = mid;
    }
    key[b] = ((unsigned)lo << 16) | (unsigned)b;
    __syncthreads();
    for (int k = 2; k <= B_; k <<= 1) {
        for (int j = k >> 1; j; j >>= 1) {
            int ixj = b ^ j;
            if (ixj > b) {
                unsigned a = key[b], c = key[ixj];
                bool up = (b & k) == 0;     // descending
                if (up ? (a < c) : (a > c)) { key[b] = c; key[ixj] = a; }
            }
            __syncthreads();
        }
    }
    g_sched[b] = (int)key[b];
}

__global__ void __launch_bounds__(128, 2) crf_kernel(
    const float* __restrict__ feats,       // [B, S, T]
    const float* __restrict__ trans,       // [T, T]
    const void*  __restrict__ tags_raw,    // [B, S] int64 OR int32 (auto-detect)
    float* __restrict__ out)
{
    __shared__ __align__(16) float wb[2][128];
    __shared__ float red[8];

    const int sched = g_sched[blockIdx.x];
    const int b   = sched & 0xFFFF;
    const int len = sched >> 16;
    const int tid  = threadIdx.x;
    const int lane = tid & 31;
    const int wid  = tid >> 5;
    const int START = T_ - 2, STOP = T_ - 1;

    // ---- detect tags dtype (int64 from jax-x64, or silently-demoted int32) ----
    int is64;
    {
        const int* t32 = (const int*)tags_raw;
        int bad = 0;
#pragma unroll
        for (int k = 0; k < 16; ++k) bad |= t32[2 * k + 1];
        is64 = (bad == 0);
    }

    // ---- E column j=tid in registers: e[m] = {exp(tr[2m][j]), exp(tr[2m+1][j])} ----
    unsigned long long e[T_ / 2];
    {
        const float* tc = trans + tid;
#pragma unroll
        for (int m = 0; m < T_ / 2; ++m) {
            float a = __expf(tc[(2 * m) * T_]);
            float c = __expf(tc[(2 * m + 1) * T_]);
            PACK2(e[m], a, c);
        }
    }
    const float tstart = trans[START * T_ + tid];
    const float tstop  = trans[tid * T_ + STOP];

    const float* fb = feats + (size_t)b * (S_ * T_);

    // ---- init: p0 = feat0 + trans[START];  w0 = exp(p0 - p0[0]);  N = p0[0] ----
    float p0 = fb[tid] + tstart;
    if (tid == 0) red[0] = p0;
    __syncthreads();
    const float m0 = red[0];
    float wreg = __expf(p0 - m0);
    wb[0][tid] = wreg;
    float N = m0;                            // identical across block

    const float* fp = fb + T_ + tid;
    float ef = __expf(*fp);                  // exp(feat[1]) ready before loop
    int buf = 0;

    for (int t = 1; t < len; ++t) {
        __syncthreads();                     // publishes wb[buf] (+ reuse guard)

        float fnext;                         // LDG issues now; exp'd at step end
        if (t + 1 < S_) fnext = fp[T_];

        const ulonglong2* wv = (const ulonglong2*)wb[buf];
        float w0 = wb[buf][0];
        float scale = __frcp_rn(w0) * 0.0078125f;   // 1/(128*w0)
        N += __logf(w0) + LOG128;            // off the critical path

        unsigned long long a0 = 0ull, a1 = 0ull, a2 = 0ull, a3 = 0ull;
        unsigned long long a4 = 0ull, a5 = 0ull, a6 = 0ull, a7 = 0ull;
#pragma unroll
        for (int k = 0; k < 32; k += 4) {
            ulonglong2 wA = wv[k];
            ulonglong2 wB = wv[k + 1];
            ulonglong2 wC = wv[k + 2];
            ulonglong2 wD = wv[k + 3];
            FMA2(a0, wA.x, e[2 * k],     a0);
            FMA2(a1, wA.y, e[2 * k + 1], a1);
            FMA2(a2, wB.x, e[2 * k + 2], a2);
            FMA2(a3, wB.y, e[2 * k + 3], a3);
            FMA2(a4, wC.x, e[2 * k + 4], a4);
            FMA2(a5, wC.y, e[2 * k + 5], a5);
            FMA2(a6, wD.x, e[2 * k + 6], a6);
            FMA2(a7, wD.y, e[2 * k + 7], a7);
        }
        ADD2(a0, a0, a4);
        ADD2(a1, a1, a5);
        ADD2(a2, a2, a6);
        ADD2(a3, a3, a7);
        ADD2(a0, a0, a2);
        ADD2(a1, a1, a3);
        ADD2(a0, a0, a1);
        float s0, s1;
        UNPACK2(s0, s1, a0);
        wreg = (s0 + s1) * (ef * scale);

        buf ^= 1;
        wb[buf][tid] = wreg;                 // STS before barrier

        // next step's exp: load is ~full step old; stall (if any) overlaps
        // the barrier wait, not the matvec.
        if (t + 1 < S_) { ef = __expf(fnext); fp += T_; }
    }

    // ---- final: forward_b = logsumexp_i(p_i + trans[i, STOP]),  p = N + log w ----
    float p = N + __logf(wreg);              // -inf for START (w=0): fine under max
    float m = warpMax(p);
    if (lane == 0) red[wid] = m;
    __syncthreads();
    m = fmaxf(fmaxf(red[0], red[1]), fmaxf(red[2], red[3]));
    float term = wreg * __expf(N - m + tstop);    // exp(p - m + tstop), 0-safe
    float ssum = warpSum(term);
    if (lane == 0) red[4 + wid] = ssum;
    __syncthreads();
    float fwd = m + __logf(red[4] + red[5] + red[6] + red[7]);

    // ---- gold path score ----
    const long long* t64 = (const long long*)tags_raw;
    const int*       t32 = (const int*)tags_raw;
    const size_t tbase = (size_t)b * S_;
    float g = 0.f;
    for (int t = tid; t < len; t += 128) {
        int tag  = is64 ? (int)t64[tbase + t] : t32[tbase + t];
        int prev = (t == 0) ? START
                            : (is64 ? (int)t64[tbase + t - 1] : t32[tbase + t - 1]);
        g += fb[t * T_ + tag] + trans[prev * T_ + tag];
    }
    g = warpSum(g);
    __syncthreads();                          // order vs red[4..7] reads above
    if (lane == 0) red[wid] = g;
    __syncthreads();

    if (tid == 0) {
        int end_id = is64 ? (int)t64[tbase + len - 1] : t32[tbase + len - 1];
        float gold = red[0] + red[1] + red[2] + red[3]
                   + trans[end_id * T_ + STOP];
        g_partial[b] = fwd - gold;
        __threadfence();
    }
    __syncthreads();

    // ---- fused deterministic final reduce (last CTA) ----
    __shared__ unsigned s_rank;
    if (tid == 0) s_rank = atomicAdd(&g_ticket, 1u);
    __syncthreads();
    if (s_rank == B_ - 1) {
        __threadfence();                      // acquire: see all g_partial
        float x = g_partial[tid] + g_partial[tid + 128];
        x = warpSum(x);
        if (lane == 0) red[wid] = x;
        __syncthreads();
        if (tid == 0) {
            out[0] = (red[0] + red[1]) + (red[2] + red[3]);
            __threadfence();
            atomicExch(&g_ticket, 0u);        // reset for next replay
        }
    }
}

extern "C" void kernel_launch(void* const* d_in, const int* in_sizes, int n_in,
                              void* d_out, int out_size) {
    const float* feats = (const float*)d_in[0];
    const float* trans = (const float*)d_in[1];
    const void*  tags  = d_in[2];
    const int*   mask  = (const int*)d_in[3];

    prep_kernel<<<1, 256>>>(mask);
    crf_kernel<<<B_, 128>>>(feats, trans, tags, (float*)d_out);
}

// round 7
// speedup vs baseline: 1.1039x; 1.1039x over previous
#include <cuda_runtime.h>

// CRF NLL, B=256, S=256, T=128 (126 tags + START/STOP)
// Two chains per CTA (grid=128, 1 CTA/SM): one __syncthreads serves two
// chain-steps, interleaved matvecs give guaranteed in-warp ILP.
// E = exp(transitions) register-resident; normalization every 4th step only
// (exact for any scale; fp32 range check: growth <= e^11/step << e^88/4steps).

#define B_    256
#define S_    256
#define T_    128
#define NCTA  128
#define LOG128 4.852030263919617f

__device__ float g_partial[B_];
__device__ int   g_sched[B_];    // (len << 16) | batch, descending by len
__device__ unsigned g_ticket;    // zero-init; reset by last CTA

#define FMA2(d, a, b, c) \
    asm("fma.rn.f32x2 %0, %1, %2, %3;" : "=l"(d) : "l"(a), "l"(b), "l"(c))
#define ADD2(d, a, b) \
    asm("add.rn.f32x2 %0, %1, %2;" : "=l"(d) : "l"(a), "l"(b))
#define PACK2(d, lo, hi) \
    asm("mov.b64 %0, {%1, %2};" : "=l"(d) : "f"(lo), "f"(hi))
#define UNPACK2(lo, hi, s) \
    asm("mov.b64 {%0, %1}, %2;" : "=f"(lo), "=f"(hi) : "l"(s))

__device__ __forceinline__ float rcpa(float x) {
    float r; asm("rcp.approx.f32 %0, %1;" : "=f"(r) : "f"(x)); return r;
}
__device__ __forceinline__ float warpMax(float x) {
#pragma unroll
    for (int o = 16; o; o >>= 1) x = fmaxf(x, __shfl_xor_sync(0xffffffffu, x, o));
    return x;
}
__device__ __forceinline__ float warpSum(float x) {
#pragma unroll
    for (int o = 16; o; o >>= 1) x += __shfl_xor_sync(0xffffffffu, x, o);
    return x;
}

// ---- prep: binary-search lengths + bitonic sort (desc) -> g_sched ----
__global__ void prep_kernel(const int* __restrict__ mask) {
    __shared__ unsigned key[B_];
    const int b = threadIdx.x;
    const int* mb = mask + b * S_;
    int lo = S_ / 2, hi = S_;               // len in [S/2, S], prefix mask
    while (lo < hi) {                       // 7 iterations
        int mid = (lo + hi) >> 1;
        if (mb[mid]) lo = mid + 1; else hi = mid;
    }
    key[b] = ((unsigned)lo << 16) | (unsigned)b;
    __syncthreads();
    for (int k = 2; k <= B_; k <<= 1) {
        for (int j = k >> 1; j; j >>= 1) {
            int ixj = b ^ j;
            if (ixj > b) {
                unsigned a = key[b], c = key[ixj];
                bool up = (b & k) == 0;     // descending
                if (up ? (a < c) : (a > c)) { key[b] = c; key[ixj] = a; }
            }
            __syncthreads();
        }
    }
    g_sched[b] = (int)key[b];
}

__global__ void __launch_bounds__(128, 1) crf_kernel(
    const float* __restrict__ feats,       // [B, S, T]
    const float* __restrict__ trans,       // [T, T]
    const void*  __restrict__ tags_raw,    // [B, S] int64 OR int32 (auto-detect)
    float* __restrict__ out)
{
    __shared__ __align__(16) float wA[2][T_];
    __shared__ __align__(16) float wB[2][T_];
    __shared__ float red[16];

    const int c  = blockIdx.x;
    const int sa = g_sched[2 * c];
    const int sb = g_sched[2 * c + 1];
    const int bA = sa & 0xFFFF, lenA = sa >> 16;   // lenA >= lenB (sorted)
    const int bB = sb & 0xFFFF, lenB = sb >> 16;
    const int lenMax = lenA;
    const int tid  = threadIdx.x;
    const int lane = tid & 31;
    const int wid  = tid >> 5;
    const int START = T_ - 2, STOP = T_ - 1;

    // ---- detect tags dtype (int64 from jax-x64, or silently-demoted int32) ----
    int is64;
    {
        const int* t32 = (const int*)tags_raw;
        int bad = 0;
#pragma unroll
        for (int k = 0; k < 16; ++k) bad |= t32[2 * k + 1];
        is64 = (bad == 0);
    }

    // ---- E column j=tid in registers: e[m] = {exp(tr[2m][j]), exp(tr[2m+1][j])} ----
    unsigned long long e[T_ / 2];
    {
        const float* tc = trans + tid;
#pragma unroll
        for (int m = 0; m < T_ / 2; ++m) {
            float a  = __expf(tc[(2 * m) * T_]);
            float cc = __expf(tc[(2 * m + 1) * T_]);
            PACK2(e[m], a, cc);
        }
    }
    const float tstart = trans[START * T_ + tid];
    const float tstop  = trans[tid * T_ + STOP];

    const float* fbA = feats + (size_t)bA * (S_ * T_);
    const float* fbB = feats + (size_t)bB * (S_ * T_);

    // ---- init both chains: w = exp(p0 - p0[0]);  N = p0[0] ----
    float pA0 = fbA[tid] + tstart;
    float pB0 = fbB[tid] + tstart;
    if (tid == 0) { red[0] = pA0; red[1] = pB0; }
    __syncthreads();
    float NA = red[0], NB = red[1];
    float wrA = __expf(pA0 - NA);
    float wrB = __expf(pB0 - NB);
    wA[0][tid] = wrA;
    wB[0][tid] = wrB;

    const float* fpA = fbA + T_ + tid;
    const float* fpB = fbB + T_ + tid;
    float efA = __expf(*fpA);               // exp(feat[1]) ready before loop
    float efB = __expf(*fpB);
    int buf = 0, t = 1;

    const int nblk = (lenMax - 1 + 3) >> 2;
    for (int blk = 0; blk < nblk; ++blk) {
#pragma unroll
        for (int u = 0; u < 4; ++u) {       // u==0 is the normalizing step
            __syncthreads();                // publishes wX[buf] (+ reuse guard)
            const int sel = (t + 1 < S_) ? T_ : 0;   // branchless clamp
            const float fnA = fpA[sel];
            const float fnB = fpB[sel];

            const ulonglong2* vA = (const ulonglong2*)wA[buf];
            const ulonglong2* vB = (const ulonglong2*)wB[buf];

            float mulA = efA, mulB = efB;
            float dNA = 0.f, dNB = 0.f;
            if (u == 0) {                   // compile-time branch (unrolled)
                float w0A = wA[buf][0], w0B = wB[buf][0];
                mulA = efA * (rcpa(w0A) * 0.0078125f);
                mulB = efB * (rcpa(w0B) * 0.0078125f);
                dNA = __logf(w0A) + LOG128;
                dNB = __logf(w0B) + LOG128;
            }

            unsigned long long a0 = 0, a1 = 0, a2 = 0, a3 = 0;
            unsigned long long b0 = 0, b1 = 0, b2 = 0, b3 = 0;
#pragma unroll
            for (int k = 0; k < 32; k += 2) {
                ulonglong2 xA = vA[k];
                ulonglong2 xB = vB[k];
                ulonglong2 yA = vA[k + 1];
                ulonglong2 yB = vB[k + 1];
                FMA2(a0, xA.x, e[2 * k],     a0);
                FMA2(b0, xB.x, e[2 * k],     b0);
                FMA2(a1, xA.y, e[2 * k + 1], a1);
                FMA2(b1, xB.y, e[2 * k + 1], b1);
                FMA2(a2, yA.x, e[2 * k + 2], a2);
                FMA2(b2, yB.x, e[2 * k + 2], b2);
                FMA2(a3, yA.y, e[2 * k + 3], a3);
                FMA2(b3, yB.y, e[2 * k + 3], b3);
            }
            ADD2(a0, a0, a2); ADD2(a1, a1, a3); ADD2(a0, a0, a1);
            ADD2(b0, b0, b2); ADD2(b1, b1, b3); ADD2(b0, b0, b1);
            float sA0, sA1, sB0, sB1;
            UNPACK2(sA0, sA1, a0);
            UNPACK2(sB0, sB1, b0);
            float nwA = (sA0 + sA1) * mulA;
            float nwB = (sB0 + sB1) * mulB;

            bool aA = (t < lenA), aB = (t < lenB);   // freeze finished chains
            wrA = aA ? nwA : wrA;
            wrB = aB ? nwB : wrB;
            if (u == 0) { NA += aA ? dNA : 0.f; NB += aB ? dNB : 0.f; }

            buf ^= 1;
            wA[buf][tid] = wrA;
            wB[buf][tid] = wrB;

            efA = __expf(fnA);              // for next step; off matvec path
            efB = __expf(fnB);
            fpA += sel; fpB += sel;
            ++t;
        }
    }

    // ---- final: forward = logsumexp_i(p_i + trans[i,STOP]),  p = N + log w ----
    float pA = NA + __logf(wrA);            // -inf for START (w=0): fine under max
    float pB = NB + __logf(wrB);
    float mA = warpMax(pA), mB = warpMax(pB);
    if (lane == 0) { red[wid] = mA; red[4 + wid] = mB; }
    __syncthreads();
    mA = fmaxf(fmaxf(red[0], red[1]), fmaxf(red[2], red[3]));
    mB = fmaxf(fmaxf(red[4], red[5]), fmaxf(red[6], red[7]));
    float tA = wrA * __expf(NA - mA + tstop);     // exp(p - m + tstop), 0-safe
    float tB = wrB * __expf(NB - mB + tstop);
    tA = warpSum(tA); tB = warpSum(tB);
    if (lane == 0) { red[8 + wid] = tA; red[12 + wid] = tB; }
    __syncthreads();
    float fwdA = mA + __logf((red[8]  + red[9])  + (red[10] + red[11]));
    float fwdB = mB + __logf((red[12] + red[13]) + (red[14] + red[15]));

    // ---- gold path scores ----
    const long long* t64 = (const long long*)tags_raw;
    const int*       t32 = (const int*)tags_raw;
    const size_t baA = (size_t)bA * S_, baB = (size_t)bB * S_;
    float gA = 0.f, gB = 0.f;
    for (int tt = tid; tt < lenA; tt += 128) {
        int tag  = is64 ? (int)t64[baA + tt] : t32[baA + tt];
        int prev = (tt == 0) ? START
                             : (is64 ? (int)t64[baA + tt - 1] : t32[baA + tt - 1]);
        gA += fbA[tt * T_ + tag] + trans[prev * T_ + tag];
    }
    for (int tt = tid; tt < lenB; tt += 128) {
        int tag  = is64 ? (int)t64[baB + tt] : t32[baB + tt];
        int prev = (tt == 0) ? START
                             : (is64 ? (int)t64[baB + tt - 1] : t32[baB + tt - 1]);
        gB += fbB[tt * T_ + tag] + trans[prev * T_ + tag];
    }
    gA = warpSum(gA); gB = warpSum(gB);
    __syncthreads();                         // red reuse guard
    if (lane == 0) { red[wid] = gA; red[4 + wid] = gB; }
    __syncthreads();

    if (tid == 0) {
        int endA = is64 ? (int)t64[baA + lenA - 1] : t32[baA + lenA - 1];
        int endB = is64 ? (int)t64[baB + lenB - 1] : t32[baB + lenB - 1];
        float goldA = (red[0] + red[1]) + (red[2] + red[3])
                    + trans[endA * T_ + STOP];
        float goldB = (red[4] + red[5]) + (red[6] + red[7])
                    + trans[endB * T_ + STOP];
        g_partial[bA] = fwdA - goldA;
        g_partial[bB] = fwdB - goldB;
        __threadfence();
    }
    __syncthreads();

    // ---- fused deterministic final reduce (last CTA) ----
    __shared__ unsigned s_rank;
    if (tid == 0) s_rank = atomicAdd(&g_ticket, 1u);
    __syncthreads();
    if (s_rank == NCTA - 1) {
        __threadfence();                      // acquire: see all g_partial
        float x = g_partial[tid] + g_partial[tid + 128];
        x = warpSum(x);
        if (lane == 0) red[wid] = x;
        __syncthreads();
        if (tid == 0) {
            out[0] = (red[0] + red[1]) + (red[2] + red[3]);
            __threadfence();
            atomicExch(&g_ticket, 0u);        // reset for next replay
        }
    }
}

extern "C" void kernel_launch(void* const* d_in, const int* in_sizes, int n_in,
                              void* d_out, int out_size) {
    const float* feats = (const float*)d_in[0];
    const float* trans = (const float*)d_in[1];
    const void*  tags  = d_in[2];
    const int*   mask  = (const int*)d_in[3];

    prep_kernel<<<1, 256>>>(mask);
    crf_kernel<<<NCTA, 128>>>(feats, trans, tags, (float*)d_out);
}

// round 8
// speedup vs baseline: 1.1676x; 1.0577x over previous
#include <cuda_runtime.h>

// CRF NLL, B=256, S=256, T=128 (126 tags + START/STOP)
// One 256-thread CTA = TWO independent 128-thread halves, one chain each,
// synchronized by per-half NAMED barriers (bar.sync 1/2, 128). Each SMSP gets
// one warp of each half -> chain A's stalls are filled by chain B's issue.
// E = exp(transitions) register-resident per thread (column j = tid&127).
// Scaled-probability recursion, per-step symmetric normalization:
//   w'_j = (sum_i w_i E[i][j]) * exp(f_j) / (128*w0),  N += log(w0)+log128.

#define B_    256
#define S_    256
#define T_    128
#define NCTA  128
#define LOG128 4.852030263919617f

__device__ float g_partial[B_];
__device__ int   g_sched[B_];    // (len << 16) | batch, descending by len
__device__ unsigned g_ticket;    // zero-init; reset by last CTA

#define FMA2(d, a, b, c) \
    asm("fma.rn.f32x2 %0, %1, %2, %3;" : "=l"(d) : "l"(a), "l"(b), "l"(c))
#define ADD2(d, a, b) \
    asm("add.rn.f32x2 %0, %1, %2;" : "=l"(d) : "l"(a), "l"(b))
#define PACK2(d, lo, hi) \
    asm("mov.b64 %0, {%1, %2};" : "=l"(d) : "f"(lo), "f"(hi))
#define UNPACK2(lo, hi, s) \
    asm("mov.b64 {%0, %1}, %2;" : "=f"(lo), "=f"(hi) : "l"(s))
#define BARH(id) \
    asm volatile("bar.sync %0, 128;" :: "r"(id) : "memory")

__device__ __forceinline__ float rcpa(float x) {
    float r; asm("rcp.approx.f32 %0, %1;" : "=f"(r) : "f"(x)); return r;
}
__device__ __forceinline__ float warpMax(float x) {
#pragma unroll
    for (int o = 16; o; o >>= 1) x = fmaxf(x, __shfl_xor_sync(0xffffffffu, x, o));
    return x;
}
__device__ __forceinline__ float warpSum(float x) {
#pragma unroll
    for (int o = 16; o; o >>= 1) x += __shfl_xor_sync(0xffffffffu, x, o);
    return x;
}

// ---- prep: binary-search lengths + bitonic sort (desc) -> g_sched ----
__global__ void prep_kernel(const int* __restrict__ mask) {
    __shared__ unsigned key[B_];
    const int b = threadIdx.x;
    const int* mb = mask + b * S_;
    int lo = S_ / 2, hi = S_;               // len in [S/2, S], prefix mask
    while (lo < hi) {                       // 7 iterations
        int mid = (lo + hi) >> 1;
        if (mb[mid]) lo = mid + 1; else hi = mid;
    }
    key[b] = ((unsigned)lo << 16) | (unsigned)b;
    __syncthreads();
    for (int k = 2; k <= B_; k <<= 1) {
        for (int j = k >> 1; j; j >>= 1) {
            int ixj = b ^ j;
            if (ixj > b) {
                unsigned a = key[b], c = key[ixj];
                bool up = (b & k) == 0;     // descending
                if (up ? (a < c) : (a > c)) { key[b] = c; key[ixj] = a; }
            }
            __syncthreads();
        }
    }
    g_sched[b] = (int)key[b];
}

__global__ void __launch_bounds__(256, 1) crf_kernel(
    const float* __restrict__ feats,       // [B, S, T]
    const float* __restrict__ trans,       // [T, T]
    const void*  __restrict__ tags_raw,    // [B, S] int64 OR int32 (auto-detect)
    float* __restrict__ out)
{
    __shared__ __align__(16) float ws[2][2][T_];   // [half][buf][j]
    __shared__ float red[2][12];                   // per-half scratch

    const int tid  = threadIdx.x;
    const int h    = tid >> 7;               // half = chain slot
    const int j    = tid & 127;              // output state
    const int lane = tid & 31;
    const int widh = (tid >> 5) & 3;         // warp within half
    const int bar  = h + 1;                  // named barrier id (1 or 2)
    const int START = T_ - 2, STOP = T_ - 1;

    const int sc  = g_sched[2 * blockIdx.x + h];   // adjacent lengths paired
    const int b   = sc & 0xFFFF;
    const int len = sc >> 16;

    // ---- detect tags dtype (int64 from jax-x64, or silently-demoted int32) ----
    int is64;
    {
        const int* t32 = (const int*)tags_raw;
        int bad = 0;
#pragma unroll
        for (int k = 0; k < 16; ++k) bad |= t32[2 * k + 1];
        is64 = (bad == 0);
    }

    // ---- E column j in registers: e[m] = {exp(tr[2m][j]), exp(tr[2m+1][j])} ----
    unsigned long long e[T_ / 2];
    {
        const float* tc = trans + j;
#pragma unroll
        for (int m = 0; m < T_ / 2; ++m) {
            float a  = __expf(tc[(2 * m) * T_]);
            float cc = __expf(tc[(2 * m + 1) * T_]);
            PACK2(e[m], a, cc);
        }
    }
    const float tstart = trans[START * T_ + j];
    const float tstop  = trans[j * T_ + STOP];

    const float* fb = feats + (size_t)b * (S_ * T_);

    // ---- init: p0 = feat0 + trans[START];  w0 = exp(p0 - p0[0]);  N = p0[0] ----
    float p0 = fb[j] + tstart;
    if (j == 0) red[h][0] = p0;
    BARH(bar);
    float N = red[h][0];
    float wreg = __expf(p0 - N);
    ws[h][0][j] = wreg;

    const float* fp = fb + T_ + j;
    float fnext = *fp;                       // feat[1], exp'd at top of t=1
    int buf = 0;

    for (int t = 1; t < len; ++t) {
        BARH(bar);                           // publishes ws[h][buf]
        const float f = fnext;               // loaded one iteration ago
        const int sel = (t + 1 < S_) ? T_ : 0;
        fp += sel;
        fnext = *fp;                         // LDG for next iteration

        const ulonglong2* vv = (const ulonglong2*)ws[h][buf];
        float w0 = ws[h][buf][0];
        float scale = rcpa(w0) * 0.0078125f;       // 1/(128*w0)
        float ef = __expf(f);                      // overlaps matvec
        N += __logf(w0) + LOG128;                  // off critical path

        unsigned long long a0 = 0, a1 = 0, a2 = 0, a3 = 0;
        unsigned long long a4 = 0, a5 = 0, a6 = 0, a7 = 0;
#pragma unroll
        for (int k = 0; k < 32; k += 4) {
            ulonglong2 x0 = vv[k];
            ulonglong2 x1 = vv[k + 1];
            ulonglong2 x2 = vv[k + 2];
            ulonglong2 x3 = vv[k + 3];
            FMA2(a0, x0.x, e[2 * k],     a0);
            FMA2(a1, x0.y, e[2 * k + 1], a1);
            FMA2(a2, x1.x, e[2 * k + 2], a2);
            FMA2(a3, x1.y, e[2 * k + 3], a3);
            FMA2(a4, x2.x, e[2 * k + 4], a4);
            FMA2(a5, x2.y, e[2 * k + 5], a5);
            FMA2(a6, x3.x, e[2 * k + 6], a6);
            FMA2(a7, x3.y, e[2 * k + 7], a7);
        }
        ADD2(a0, a0, a4); ADD2(a1, a1, a5);
        ADD2(a2, a2, a6); ADD2(a3, a3, a7);
        ADD2(a0, a0, a2); ADD2(a1, a1, a3);
        ADD2(a0, a0, a1);
        float s0, s1;
        UNPACK2(s0, s1, a0);
        wreg = (s0 + s1) * (ef * scale);

        buf ^= 1;
        ws[h][buf][j] = wreg;                // STS before next barrier
    }

    // ---- final: forward = logsumexp_i(p_i + trans[i,STOP]),  p = N + log w ----
    float p = N + __logf(wreg);              // -inf for START (w=0): fine under max
    float m = warpMax(p);
    if (lane == 0) red[h][widh] = m;
    BARH(bar);
    m = fmaxf(fmaxf(red[h][0], red[h][1]), fmaxf(red[h][2], red[h][3]));
    float term = wreg * __expf(N - m + tstop);     // exp(p - m + tstop), 0-safe
    term = warpSum(term);
    if (lane == 0) red[h][4 + widh] = term;
    BARH(bar);
    float fwd = m + __logf((red[h][4] + red[h][5]) + (red[h][6] + red[h][7]));

    // ---- gold path score (128 threads of this half) ----
    const long long* t64 = (const long long*)tags_raw;
    const int*       t32 = (const int*)tags_raw;
    const size_t tbase = (size_t)b * S_;
    float g = 0.f;
    for (int tt = j; tt < len; tt += 128) {
        int tag  = is64 ? (int)t64[tbase + tt] : t32[tbase + tt];
        int prev = (tt == 0) ? START
                             : (is64 ? (int)t64[tbase + tt - 1] : t32[tbase + tt - 1]);
        g += fb[tt * T_ + tag] + trans[prev * T_ + tag];
    }
    g = warpSum(g);
    if (lane == 0) red[h][8 + widh] = g;
    BARH(bar);

    if (j == 0) {
        int end_id = is64 ? (int)t64[tbase + len - 1] : t32[tbase + len - 1];
        float gold = (red[h][8] + red[h][9]) + (red[h][10] + red[h][11])
                   + trans[end_id * T_ + STOP];
        g_partial[b] = fwd - gold;
        __threadfence();
    }
    __syncthreads();                          // both halves done

    // ---- fused deterministic final reduce (last CTA) ----
    __shared__ unsigned s_rank;
    if (tid == 0) s_rank = atomicAdd(&g_ticket, 1u);
    __syncthreads();
    if (s_rank == NCTA - 1) {
        __threadfence();                      // acquire: see all g_partial
        float x = g_partial[tid];             // 256 threads = 256 batches
        x = warpSum(x);
        __shared__ float sb[8];
        if (lane == 0) sb[tid >> 5] = x;
        __syncthreads();
        if (tid == 0) {
            float s = 0.f;
#pragma unroll
            for (int i = 0; i < 8; ++i) s += sb[i];
            out[0] = s;
            __threadfence();
            atomicExch(&g_ticket, 0u);        // reset for next replay
        }
    }
}

extern "C" void kernel_launch(void* const* d_in, const int* in_sizes, int n_in,
                              void* d_out, int out_size) {
    const float* feats = (const float*)d_in[0];
    const float* trans = (const float*)d_in[1];
    const void*  tags  = d_in[2];
    const int*   mask  = (const int*)d_in[3];

    prep_kernel<<<1, 256>>>(mask);
    crf_kernel<<<NCTA, 256>>>(feats, trans, tags, (float*)d_out);
}